// round 8
// baseline (speedup 1.0000x reference)
#include <cuda_runtime.h>

// Problem constants
#define BB   32
#define CIN  64
#define OCH  128
#define HH   64
#define WW   64
#define PP   (HH*WW)          // 4096 pixels
#define OH   32
#define OW   32
#define SLICE ((size_t)BB*OCH*OH*OW)   // elements per output slice

typedef unsigned long long u64;

// Scratch (device globals: no allocation allowed in kernel_launch)
__device__ float g_l1  [BB*OCH*HH*WW];
__device__ float g_l2  [BB*OCH*HH*WW];
__device__ float g_l3  [BB*OCH*HH*WW];
__device__ float g_prev[BB*OCH*HH*WW];
__device__ float g_aux [BB*OCH*OH*OW];
__device__ float g_attn[BB*PP];

__device__ __forceinline__ float lrelu(float x) { return x >= 0.f ? x : 0.1f * x; }

// ---- packed f32x2 helpers (sm_103a) -----------------------------------
__device__ __forceinline__ u64 pk2(float lo, float hi) {
    u64 r; asm("mov.b64 %0,{%1,%2};" : "=l"(r) : "f"(lo), "f"(hi)); return r;
}
__device__ __forceinline__ u64 splat(float v) { return pk2(v, v); }
__device__ __forceinline__ void fma2(u64& d, u64 a, u64 b) {
    asm("fma.rn.f32x2 %0,%1,%2,%0;" : "+l"(d) : "l"(a), "l"(b));
}
__device__ __forceinline__ float2 unpk(u64 v) {
    float2 r; asm("mov.b64 {%0,%1},%2;" : "=f"(r.x), "=f"(r.y) : "l"(v)); return r;
}

// ---------------------------------------------------------------------------
// Attention: logits[b,p] = <lin_w[p,:], out1[b,:,p]> + lin_b[p]; softmax over p.
// ---------------------------------------------------------------------------
__global__ void attn_kernel(const float* __restrict__ out1,
                            const float* __restrict__ lin_w,
                            const float* __restrict__ lin_b,
                            float* __restrict__ attn)
{
    const int b   = blockIdx.x;
    const int tid = threadIdx.x;
    const float* xb = out1 + (size_t)b * CIN * PP;

    float logit[16];
    float lmax = -1e30f;
#pragma unroll
    for (int i = 0; i < 16; i++) {
        const int p = tid + i * 256;
        float acc = lin_b[p];
        const float4* wr = (const float4*)(lin_w + (size_t)p * CIN);
#pragma unroll
        for (int c4 = 0; c4 < CIN / 4; c4++) {
            float4 w4 = wr[c4];
            acc = fmaf(w4.x, xb[(c4*4+0)*PP + p], acc);
            acc = fmaf(w4.y, xb[(c4*4+1)*PP + p], acc);
            acc = fmaf(w4.z, xb[(c4*4+2)*PP + p], acc);
            acc = fmaf(w4.w, xb[(c4*4+3)*PP + p], acc);
        }
        logit[i] = acc;
        lmax = fmaxf(lmax, acc);
    }

    __shared__ float red[256];
    red[tid] = lmax; __syncthreads();
    for (int s = 128; s > 0; s >>= 1) {
        if (tid < s) red[tid] = fmaxf(red[tid], red[tid + s]);
        __syncthreads();
    }
    const float m = red[0]; __syncthreads();

    float lsum = 0.f;
#pragma unroll
    for (int i = 0; i < 16; i++) { logit[i] = expf(logit[i] - m); lsum += logit[i]; }
    red[tid] = lsum; __syncthreads();
    for (int s = 128; s > 0; s >>= 1) {
        if (tid < s) red[tid] += red[tid + s];
        __syncthreads();
    }
    const float inv = 1.0f / red[0];
#pragma unroll
    for (int i = 0; i < 16; i++)
        attn[(size_t)b * PP + tid + i * 256] = logit[i] * inv;
}

// ---------------------------------------------------------------------------
// Stride-1 3x3 conv + bias + lrelu, f32x2 over oc pairs, software-pipelined.
// Input tile stored PRE-SPLATTED in smem (u64 (v,v) per pixel): the compute
// loop reads 10 splats per k-row via 5 LDS.128 — zero MOVs in the hot loop.
// Block: tile 32 rows x 64 cols, 8 oc (4 pairs), 256 threads.
// ---------------------------------------------------------------------------
template<int CI>
__global__ __launch_bounds__(256, 2)
void conv_s1(const float* __restrict__ in0, const float* __restrict__ in1, int csplit,
             const float* __restrict__ wgt, const float* __restrict__ bias,
             float* __restrict__ out)
{
    __shared__ __align__(16) u64 s_in[2][34][68];   // pre-splatted pixels
    __shared__ __align__(16) u64 s_w[2][4][12];     // [buf][oc2][k*4+t]

    const int tid  = threadIdx.x;
    const int tx   = tid & 7;
    const int ty   = tid >> 3;
    const int x8   = tx * 8;
    const int ty0  = blockIdx.x * 32;
    const int ocg  = blockIdx.y;
    const int b    = blockIdx.z;
    const int warp = tid >> 5;
    const int lane = tid & 31;

    // weight element handled by this thread (fixed across chunks)
    const int woc = tid / 9, wkk = tid - woc * 9;
    const int wk  = wkk / 3, wt = wkk - wk * 3;
    const bool wme = tid < 72;

    u64 acc2[4][8];
#pragma unroll
    for (int o = 0; o < 4; o++)
#pragma unroll
        for (int j = 0; j < 8; j++) acc2[o][j] = 0ULL;

    float pfA[5], pfB[5], pfE[5], wv = 0.f;

    auto load_chunk = [&](int cg) {
        const float* src = (cg < csplit)
            ? in0 + ((size_t)b * csplit + cg) * PP
            : in1 + ((size_t)b * (CI - csplit) + (cg - csplit)) * PP;
#pragma unroll
        for (int k = 0; k < 5; k++) {
            const int iy = warp + 8*k;
            const int gy = ty0 - 1 + iy;
            const bool rowok = (iy < 34) & ((unsigned)gy < HH);
            const float* rowp = src + gy * WW;
            pfA[k] = (rowok && (unsigned)(lane - 1) < WW) ? rowp[lane - 1] : 0.f;
            pfB[k] = (rowok && lane + 31 < WW)            ? rowp[lane + 31] : 0.f;
            pfE[k] = (rowok && lane < 2 && lane + 63 < WW)? rowp[lane + 63] : 0.f;
        }
        if (wme) wv = wgt[((size_t)(ocg*8 + woc) * CI + cg) * 9 + wkk];
    };
    auto store_chunk = [&](int bf) {
#pragma unroll
        for (int k = 0; k < 5; k++) {
            const int iy = warp + 8*k;
            if (k < 4 || iy < 34) {
                u64* srow = &s_in[bf][iy][0];
                srow[lane]      = splat(pfA[k]);
                srow[lane + 32] = splat(pfB[k]);
                if (lane < 2) srow[lane + 64] = splat(pfE[k]);
            }
        }
        if (wme) ((float*)&s_w[bf][woc >> 1][wk*4 + wt])[woc & 1] = wv;
    };

    // prologue
    load_chunk(0);
    store_chunk(0);
    __syncthreads();

    for (int c = 0; c < CI; c++) {
        const int bf = c & 1;
        if (c + 1 < CI) load_chunk(c + 1);          // LDG only, no consumer yet

        // compute chunk c: splats come straight from smem (LDS.128 pairs)
#pragma unroll
        for (int k = 0; k < 3; k++) {
            const ulonglong2* rp = (const ulonglong2*)&s_in[bf][ty + k][x8];
            const ulonglong2 q0 = rp[0], q1 = rp[1], q2 = rp[2], q3 = rp[3], q4 = rp[4];
            const u64 rs[10] = {q0.x, q0.y, q1.x, q1.y, q2.x,
                                q2.y, q3.x, q3.y, q4.x, q4.y};
#pragma unroll
            for (int o2 = 0; o2 < 4; o2++) {
                const ulonglong2 w01 = *(const ulonglong2*)&s_w[bf][o2][k*4];
                const u64 w2 = s_w[bf][o2][k*4 + 2];
#pragma unroll
                for (int j = 0; j < 8; j++) {
                    fma2(acc2[o2][j], rs[j],     w01.x);
                    fma2(acc2[o2][j], rs[j + 1], w01.y);
                    fma2(acc2[o2][j], rs[j + 2], w2);
                }
            }
        }

        if (c + 1 < CI) store_chunk(bf ^ 1);        // other buffer: no WAR
        __syncthreads();
    }

#pragma unroll
    for (int o2 = 0; o2 < 4; o2++) {
        const float b0 = bias[ocg*8 + 2*o2];
        const float b1 = bias[ocg*8 + 2*o2 + 1];
        float r0[8], r1[8];
#pragma unroll
        for (int j = 0; j < 8; j++) {
            float2 v = unpk(acc2[o2][j]);
            r0[j] = lrelu(v.x + b0);
            r1[j] = lrelu(v.y + b1);
        }
        size_t o0 = (((size_t)b * OCH + ocg*8 + 2*o2)     * HH + ty0 + ty) * WW + x8;
        size_t o1 = (((size_t)b * OCH + ocg*8 + 2*o2 + 1) * HH + ty0 + ty) * WW + x8;
        *(float4*)(out + o0)     = make_float4(r0[0], r0[1], r0[2], r0[3]);
        *(float4*)(out + o0 + 4) = make_float4(r0[4], r0[5], r0[6], r0[7]);
        *(float4*)(out + o1)     = make_float4(r1[0], r1[1], r1[2], r1[3]);
        *(float4*)(out + o1 + 4) = make_float4(r1[4], r1[5], r1[6], r1[7]);
    }
}

// ---------------------------------------------------------------------------
// Stride-2 3x3 conv + bias + lrelu (pad 1), out 32x32, pipelined, 16 oc/block.
// Pre-splatted input tile in DYNAMIC smem (72.3 KB > 48 KB static limit).
// ---------------------------------------------------------------------------
#define S2_IN_ELEMS  (2*65*68)
#define S2_SMEM_B    ((S2_IN_ELEMS + 2*8*12) * 8)

template<int CI>
__global__ __launch_bounds__(256, 2)
void conv_s2(const float* __restrict__ in0, const float* __restrict__ in1, int csplit,
             const float* __restrict__ wgt, const float* __restrict__ bias,
             float* __restrict__ out)
{
    extern __shared__ __align__(16) u64 dynsmem[];
    u64 (*s_in)[65][68] = (u64(*)[65][68])dynsmem;                 // [2][65][68]
    u64 (*s_w)[8][12]   = (u64(*)[8][12])(dynsmem + S2_IN_ELEMS);  // [2][8][12]

    const int tid  = threadIdx.x;
    const int tx   = tid & 7;           // out col group (4 cols)
    const int ty   = tid >> 3;          // 0..31 out row
    const int ocg  = blockIdx.y;        // 0..7
    const int b    = blockIdx.z;
    const int warp = tid >> 5;
    const int lane = tid & 31;

    const int woc = tid / 9, wkk = tid - woc * 9;
    const int wk  = wkk / 3, wt = wkk - wk * 3;
    const bool wme = tid < 144;         // 16 oc x 9

    u64 acc2[8][4];
#pragma unroll
    for (int o = 0; o < 8; o++)
#pragma unroll
        for (int j = 0; j < 4; j++) acc2[o][j] = 0ULL;

    float pfA[9], pfB[9], pfE[9], wv = 0.f;

    auto load_chunk = [&](int cg) {
        const float* src = (cg < csplit)
            ? in0 + ((size_t)b * csplit + cg) * PP
            : in1 + ((size_t)b * (CI - csplit) + (cg - csplit)) * PP;
#pragma unroll
        for (int k = 0; k < 9; k++) {
            const int iy = warp + 8*k;
            const int gy = iy - 1;
            const bool rowok = (iy < 65) & ((unsigned)gy < HH);
            const float* rowp = src + gy * WW;
            pfA[k] = (rowok && (unsigned)(lane - 1) < WW) ? rowp[lane - 1] : 0.f;
            pfB[k] = (rowok && lane + 31 < WW)            ? rowp[lane + 31] : 0.f;
            pfE[k] = (rowok && lane == 0)                 ? rowp[63]        : 0.f;
        }
        if (wme) wv = wgt[((size_t)(ocg*16 + woc) * CI + cg) * 9 + wkk];
    };
    auto store_chunk = [&](int bf) {
#pragma unroll
        for (int k = 0; k < 9; k++) {
            const int iy = warp + 8*k;
            if (k < 8 || iy < 65) {
                u64* srow = &s_in[bf][iy][0];
                srow[lane]      = splat(pfA[k]);
                srow[lane + 32] = splat(pfB[k]);
                if (lane == 0) srow[64] = splat(pfE[k]);
            }
        }
        if (wme) ((float*)&s_w[bf][woc >> 1][wk*4 + wt])[woc & 1] = wv;
    };

    load_chunk(0);
    store_chunk(0);
    __syncthreads();

    for (int c = 0; c < CI; c++) {
        const int bf = c & 1;
        if (c + 1 < CI) load_chunk(c + 1);

#pragma unroll
        for (int k = 0; k < 3; k++) {
            const ulonglong2* rp = (const ulonglong2*)&s_in[bf][2*ty + k][8*tx];
            const ulonglong2 q0 = rp[0], q1 = rp[1], q2 = rp[2], q3 = rp[3], q4 = rp[4];
            const u64 rs[10] = {q0.x, q0.y, q1.x, q1.y, q2.x,
                                q2.y, q3.x, q3.y, q4.x, q4.y};
#pragma unroll
            for (int o2 = 0; o2 < 8; o2++) {
                const ulonglong2 w01 = *(const ulonglong2*)&s_w[bf][o2][k*4];
                const u64 w2 = s_w[bf][o2][k*4 + 2];
#pragma unroll
                for (int j = 0; j < 4; j++) {
                    fma2(acc2[o2][j], rs[2*j],     w01.x);
                    fma2(acc2[o2][j], rs[2*j + 1], w01.y);
                    fma2(acc2[o2][j], rs[2*j + 2], w2);
                }
            }
        }

        if (c + 1 < CI) store_chunk(bf ^ 1);
        __syncthreads();
    }

#pragma unroll
    for (int o2 = 0; o2 < 8; o2++) {
        const float b0 = bias[ocg*16 + 2*o2];
        const float b1 = bias[ocg*16 + 2*o2 + 1];
        float r0[4], r1[4];
#pragma unroll
        for (int j = 0; j < 4; j++) {
            float2 v = unpk(acc2[o2][j]);
            r0[j] = lrelu(v.x + b0);
            r1[j] = lrelu(v.y + b1);
        }
        size_t oo0 = (((size_t)b * OCH + ocg*16 + 2*o2)     * OH + ty) * OW + tx*4;
        size_t oo1 = (((size_t)b * OCH + ocg*16 + 2*o2 + 1) * OH + ty) * OW + tx*4;
        *(float4*)(out + oo0) = make_float4(r0[0], r0[1], r0[2], r0[3]);
        *(float4*)(out + oo1) = make_float4(r1[0], r1[1], r1[2], r1[3]);
    }
}

// ---------------------------------------------------------------------------
// RoIAlign(full image, 32x32 bins, sampling_ratio=2) of prev*attn -> slice 2.
// ---------------------------------------------------------------------------
__global__ void bo3_kernel(const float* __restrict__ prev,
                           const float* __restrict__ attn,
                           float* __restrict__ out /* slice-2 base */)
{
    const int idx = blockIdx.x * 256 + threadIdx.x;
    const int ox = idx & 31, oy = (idx >> 5) & 31, bc = idx >> 10;
    const int b = bc >> 7;
    const float* pv = prev + (size_t)bc * PP;
    const float* at = attn + (size_t)b * PP;
    const float BIN = 63.0f / 32.0f;

    float acc = 0.f;
#pragma unroll
    for (int sy = 0; sy < 2; sy++) {
        const float ys = ((float)oy + 0.25f + 0.5f * sy) * BIN;
        const int y0 = (int)ys;
        const int y1 = min(y0 + 1, HH - 1);
        const float ly = ys - (float)y0, hy = 1.f - ly;
#pragma unroll
        for (int sx = 0; sx < 2; sx++) {
            const float xs = ((float)ox + 0.25f + 0.5f * sx) * BIN;
            const int x0 = (int)xs;
            const int x1 = min(x0 + 1, WW - 1);
            const float lx = xs - (float)x0, hx = 1.f - lx;
            const float f00 = pv[y0*WW + x0] * at[y0*WW + x0];
            const float f01 = pv[y0*WW + x1] * at[y0*WW + x1];
            const float f10 = pv[y1*WW + x0] * at[y1*WW + x0];
            const float f11 = pv[y1*WW + x1] * at[y1*WW + x1];
            acc += hy * (hx * f00 + lx * f01) + ly * (hx * f10 + lx * f11);
        }
    }
    out[idx] = acc * 0.25f;
}

// ---------------------------------------------------------------------------
// slice0 = RoIAlign(l2) + aux + slice1 + slice2
// ---------------------------------------------------------------------------
__global__ void combine_kernel(const float* __restrict__ l2,
                               const float* __restrict__ aux,
                               float* __restrict__ out /* full d_out */)
{
    const int idx = blockIdx.x * 256 + threadIdx.x;
    const int ox = idx & 31, oy = (idx >> 5) & 31, bc = idx >> 10;
    const float* src = l2 + (size_t)bc * PP;
    const float BIN = 63.0f / 32.0f;

    float acc = 0.f;
#pragma unroll
    for (int sy = 0; sy < 2; sy++) {
        const float ys = ((float)oy + 0.25f + 0.5f * sy) * BIN;
        const int y0 = (int)ys;
        const int y1 = min(y0 + 1, HH - 1);
        const float ly = ys - (float)y0, hy = 1.f - ly;
#pragma unroll
        for (int sx = 0; sx < 2; sx++) {
            const float xs = ((float)ox + 0.25f + 0.5f * sx) * BIN;
            const int x0 = (int)xs;
            const int x1 = min(x0 + 1, WW - 1);
            const float lx = xs - (float)x0, hx = 1.f - lx;
            acc += hy * (hx * src[y0*WW + x0] + lx * src[y0*WW + x1])
                 + ly * (hx * src[y1*WW + x0] + lx * src[y1*WW + x1]);
        }
    }
    out[idx] = acc * 0.25f + aux[idx] + out[SLICE + idx] + out[2*SLICE + idx];
}

// ---------------------------------------------------------------------------
extern "C" void kernel_launch(void* const* d_in, const int* in_sizes, int n_in,
                              void* d_out, int out_size)
{
    const float* out1   = (const float*)d_in[0];
    const float* out2   = (const float*)d_in[1];
    const float* out3   = (const float*)d_in[2];
    const float* w1     = (const float*)d_in[3];
    const float* b1     = (const float*)d_in[4];
    const float* w2     = (const float*)d_in[5];
    const float* b2     = (const float*)d_in[6];
    const float* w3     = (const float*)d_in[7];
    const float* b3     = (const float*)d_in[8];
    const float* w_aux  = (const float*)d_in[9];
    const float* b_aux  = (const float*)d_in[10];
    const float* w_b2   = (const float*)d_in[11];
    const float* b_b2   = (const float*)d_in[12];
    const float* w_prev = (const float*)d_in[13];
    const float* b_prev = (const float*)d_in[14];
    const float* lin_w  = (const float*)d_in[15];
    const float* lin_b  = (const float*)d_in[16];
    float* out = (float*)d_out;

    float *l1, *l2, *l3, *prev, *aux, *attn;
    cudaGetSymbolAddress((void**)&l1,   g_l1);
    cudaGetSymbolAddress((void**)&l2,   g_l2);
    cudaGetSymbolAddress((void**)&l3,   g_l3);
    cudaGetSymbolAddress((void**)&prev, g_prev);
    cudaGetSymbolAddress((void**)&aux,  g_aux);
    cudaGetSymbolAddress((void**)&attn, g_attn);

    // dynamic-smem opt-in for conv_s2 (72.3 KB > 48 KB static limit)
    cudaFuncSetAttribute(conv_s2<256>, cudaFuncAttributeMaxDynamicSharedMemorySize, S2_SMEM_B);
    cudaFuncSetAttribute(conv_s2<128>, cudaFuncAttributeMaxDynamicSharedMemorySize, S2_SMEM_B);

    const dim3 gs1(2, OCH/8, BB);    // stride-1 convs
    const dim3 gs2(1, OCH/16, BB);   // stride-2 convs: 16 oc per block
    const int  nPix = (int)(SLICE / 256);

    attn_kernel<<<BB, 256>>>(out1, lin_w, lin_b, attn);

    conv_s1<64 ><<<gs1, 256>>>(out1, nullptr, 64,  w1,     b1,     l1);
    conv_s1<128><<<gs1, 256>>>(l1,   nullptr, 128, w2,     b2,     l2);
    conv_s1<128><<<gs1, 256>>>(l2,   nullptr, 128, w3,     b3,     l3);
    conv_s1<128><<<gs1, 256>>>(out2, out3,    64,  w_prev, b_prev, prev);

    conv_s2<256><<<gs2, 256, S2_SMEM_B>>>(l1, l2,      128, w_b2,  b_b2,  out + SLICE);
    conv_s2<128><<<gs2, 256, S2_SMEM_B>>>(l3, nullptr, 128, w_aux, b_aux, aux);

    bo3_kernel<<<nPix, 256>>>(prev, attn, out + 2*SLICE);                      // block_out3
    combine_kernel<<<nPix, 256>>>(l2, aux, out);                               // block_out1 sum
}

// round 9
// speedup vs baseline: 1.7059x; 1.7059x over previous
#include <cuda_runtime.h>

// Problem constants
#define BB   32
#define CIN  64
#define OCH  128
#define HH   64
#define WW   64
#define PP   (HH*WW)          // 4096 pixels
#define OH   32
#define OW   32
#define SLICE ((size_t)BB*OCH*OH*OW)   // elements per output slice

typedef unsigned long long u64;

// Scratch (device globals: no allocation allowed in kernel_launch)
__device__ float g_l1  [BB*OCH*HH*WW];
__device__ float g_l2  [BB*OCH*HH*WW];
__device__ float g_l3  [BB*OCH*HH*WW];
__device__ float g_prev[BB*OCH*HH*WW];
__device__ float g_aux [BB*OCH*OH*OW];
__device__ float g_attn[BB*PP];

__device__ __forceinline__ float lrelu(float x) { return x >= 0.f ? x : 0.1f * x; }

// ---- packed f32x2 helpers (sm_103a) -----------------------------------
__device__ __forceinline__ u64 pk2(float lo, float hi) {
    u64 r; asm("mov.b64 %0,{%1,%2};" : "=l"(r) : "f"(lo), "f"(hi)); return r;
}
__device__ __forceinline__ u64 splat(float v) { return pk2(v, v); }
__device__ __forceinline__ void fma2(u64& d, u64 a, u64 b) {
    asm("fma.rn.f32x2 %0,%1,%2,%0;" : "+l"(d) : "l"(a), "l"(b));
}
__device__ __forceinline__ float2 unpk(u64 v) {
    float2 r; asm("mov.b64 {%0,%1},%2;" : "=f"(r.x), "=f"(r.y) : "l"(v)); return r;
}

// ---------------------------------------------------------------------------
// Attention: logits[b,p] = <lin_w[p,:], out1[b,:,p]> + lin_b[p]; softmax over p.
// ---------------------------------------------------------------------------
__global__ void attn_kernel(const float* __restrict__ out1,
                            const float* __restrict__ lin_w,
                            const float* __restrict__ lin_b,
                            float* __restrict__ attn)
{
    const int b   = blockIdx.x;
    const int tid = threadIdx.x;
    const float* xb = out1 + (size_t)b * CIN * PP;

    float logit[16];
    float lmax = -1e30f;
#pragma unroll
    for (int i = 0; i < 16; i++) {
        const int p = tid + i * 256;
        float acc = lin_b[p];
        const float4* wr = (const float4*)(lin_w + (size_t)p * CIN);
#pragma unroll
        for (int c4 = 0; c4 < CIN / 4; c4++) {
            float4 w4 = wr[c4];
            acc = fmaf(w4.x, xb[(c4*4+0)*PP + p], acc);
            acc = fmaf(w4.y, xb[(c4*4+1)*PP + p], acc);
            acc = fmaf(w4.z, xb[(c4*4+2)*PP + p], acc);
            acc = fmaf(w4.w, xb[(c4*4+3)*PP + p], acc);
        }
        logit[i] = acc;
        lmax = fmaxf(lmax, acc);
    }

    __shared__ float red[256];
    red[tid] = lmax; __syncthreads();
    for (int s = 128; s > 0; s >>= 1) {
        if (tid < s) red[tid] = fmaxf(red[tid], red[tid + s]);
        __syncthreads();
    }
    const float m = red[0]; __syncthreads();

    float lsum = 0.f;
#pragma unroll
    for (int i = 0; i < 16; i++) { logit[i] = expf(logit[i] - m); lsum += logit[i]; }
    red[tid] = lsum; __syncthreads();
    for (int s = 128; s > 0; s >>= 1) {
        if (tid < s) red[tid] += red[tid + s];
        __syncthreads();
    }
    const float inv = 1.0f / red[0];
#pragma unroll
    for (int i = 0; i < 16; i++)
        attn[(size_t)b * PP + tid + i * 256] = logit[i] * inv;
}

// ---------------------------------------------------------------------------
// Stride-1 3x3 conv + bias + lrelu, f32x2 over oc pairs, software-pipelined:
// per ci-step: prefetch next ci to registers, compute current from smem buf,
// store prefetch to other buf, ONE barrier. Fill latency fully hidden.
// Block: tile 32 rows x 64 cols, 8 oc (4 pairs), 256 threads.
// ---------------------------------------------------------------------------
template<int CI>
__global__ __launch_bounds__(256, 2)
void conv_s1(const float* __restrict__ in0, const float* __restrict__ in1, int csplit,
             const float* __restrict__ wgt, const float* __restrict__ bias,
             float* __restrict__ out)
{
    __shared__ __align__(16) float s_in[2][34][68];   // double-buffered 1-ci tile
    __shared__ __align__(16) u64   s_w[2][4][12];     // [buf][oc2][k*4+t]

    const int tid  = threadIdx.x;
    const int tx   = tid & 7;
    const int ty   = tid >> 3;
    const int x8   = tx * 8;
    const int ty0  = blockIdx.x * 32;
    const int ocg  = blockIdx.y;
    const int b    = blockIdx.z;
    const int warp = tid >> 5;
    const int lane = tid & 31;

    // weight element handled by this thread (fixed across chunks)
    const int woc = tid / 9, wkk = tid - woc * 9;
    const int wk  = wkk / 3, wt = wkk - wk * 3;
    const bool wme = tid < 72;

    u64 acc2[4][8];
#pragma unroll
    for (int o = 0; o < 4; o++)
#pragma unroll
        for (int j = 0; j < 8; j++) acc2[o][j] = 0ULL;

    float pfA[5], pfB[5], pfE[5], wv = 0.f;

    auto load_chunk = [&](int cg) {
        const float* src = (cg < csplit)
            ? in0 + ((size_t)b * csplit + cg) * PP
            : in1 + ((size_t)b * (CI - csplit) + (cg - csplit)) * PP;
#pragma unroll
        for (int k = 0; k < 5; k++) {
            const int iy = warp + 8*k;
            const int gy = ty0 - 1 + iy;
            const bool rowok = (iy < 34) & ((unsigned)gy < HH);
            const float* rowp = src + gy * WW;
            pfA[k] = (rowok && (unsigned)(lane - 1) < WW) ? rowp[lane - 1] : 0.f;
            pfB[k] = (rowok && lane + 31 < WW)            ? rowp[lane + 31] : 0.f;
            pfE[k] = (rowok && lane < 2 && lane + 63 < WW)? rowp[lane + 63] : 0.f;
        }
        if (wme) wv = wgt[((size_t)(ocg*8 + woc) * CI + cg) * 9 + wkk];
    };
    auto store_chunk = [&](int bf) {
#pragma unroll
        for (int k = 0; k < 5; k++) {
            const int iy = warp + 8*k;
            if (k < 4 || iy < 34) {
                float* srow = &s_in[bf][iy][0];
                srow[lane]      = pfA[k];
                srow[lane + 32] = pfB[k];
                if (lane < 2) srow[lane + 64] = pfE[k];
            }
        }
        if (wme) ((float*)&s_w[bf][woc >> 1][wk*4 + wt])[woc & 1] = wv;
    };

    // prologue
    load_chunk(0);
    store_chunk(0);
    __syncthreads();

    for (int c = 0; c < CI; c++) {
        const int bf = c & 1;
        if (c + 1 < CI) load_chunk(c + 1);          // LDG only, no consumer yet

        // compute chunk c
#pragma unroll
        for (int k = 0; k < 3; k++) {
            const float4* rp = (const float4*)&s_in[bf][ty + k][x8];
            const float4 ra = rp[0], rb = rp[1], rc = rp[2];
            u64 rs[10];
            rs[0] = splat(ra.x); rs[1] = splat(ra.y); rs[2] = splat(ra.z); rs[3] = splat(ra.w);
            rs[4] = splat(rb.x); rs[5] = splat(rb.y); rs[6] = splat(rb.z); rs[7] = splat(rb.w);
            rs[8] = splat(rc.x); rs[9] = splat(rc.y);
#pragma unroll
            for (int o2 = 0; o2 < 4; o2++) {
                const ulonglong2 w01 = *(const ulonglong2*)&s_w[bf][o2][k*4];
                const u64 w2 = s_w[bf][o2][k*4 + 2];
#pragma unroll
                for (int j = 0; j < 8; j++) {
                    fma2(acc2[o2][j], rs[j],     w01.x);
                    fma2(acc2[o2][j], rs[j + 1], w01.y);
                    fma2(acc2[o2][j], rs[j + 2], w2);
                }
            }
        }

        if (c + 1 < CI) store_chunk(bf ^ 1);        // other buffer: no WAR
        __syncthreads();
    }

#pragma unroll
    for (int o2 = 0; o2 < 4; o2++) {
        const float b0 = bias[ocg*8 + 2*o2];
        const float b1 = bias[ocg*8 + 2*o2 + 1];
        float r0[8], r1[8];
#pragma unroll
        for (int j = 0; j < 8; j++) {
            float2 v = unpk(acc2[o2][j]);
            r0[j] = lrelu(v.x + b0);
            r1[j] = lrelu(v.y + b1);
        }
        size_t o0 = (((size_t)b * OCH + ocg*8 + 2*o2)     * HH + ty0 + ty) * WW + x8;
        size_t o1 = (((size_t)b * OCH + ocg*8 + 2*o2 + 1) * HH + ty0 + ty) * WW + x8;
        *(float4*)(out + o0)     = make_float4(r0[0], r0[1], r0[2], r0[3]);
        *(float4*)(out + o0 + 4) = make_float4(r0[4], r0[5], r0[6], r0[7]);
        *(float4*)(out + o1)     = make_float4(r1[0], r1[1], r1[2], r1[3]);
        *(float4*)(out + o1 + 4) = make_float4(r1[4], r1[5], r1[6], r1[7]);
    }
}

// ---------------------------------------------------------------------------
// Stride-2 3x3 conv + bias + lrelu (pad 1), out 32x32, pipelined like conv_s1.
// Block: 16 oc (8 pairs), 256 threads; thread: 1 out row x 4 cols x 8 pairs.
// ---------------------------------------------------------------------------
template<int CI>
__global__ __launch_bounds__(256, 2)
void conv_s2(const float* __restrict__ in0, const float* __restrict__ in1, int csplit,
             const float* __restrict__ wgt, const float* __restrict__ bias,
             float* __restrict__ out)
{
    __shared__ __align__(16) float s_in[2][65][68];   // rows -1..63, cols -1..63
    __shared__ __align__(16) u64   s_w[2][8][12];     // [buf][oc2][k*4+t]

    const int tid  = threadIdx.x;
    const int tx   = tid & 7;           // out col group (4 cols)
    const int ty   = tid >> 3;          // 0..31 out row
    const int ocg  = blockIdx.y;        // 0..7
    const int b    = blockIdx.z;
    const int warp = tid >> 5;
    const int lane = tid & 31;

    const int woc = tid / 9, wkk = tid - woc * 9;
    const int wk  = wkk / 3, wt = wkk - wk * 3;
    const bool wme = tid < 144;         // 16 oc x 9

    u64 acc2[8][4];
#pragma unroll
    for (int o = 0; o < 8; o++)
#pragma unroll
        for (int j = 0; j < 4; j++) acc2[o][j] = 0ULL;

    float pfA[9], pfB[9], pfE[9], wv = 0.f;

    auto load_chunk = [&](int cg) {
        const float* src = (cg < csplit)
            ? in0 + ((size_t)b * csplit + cg) * PP
            : in1 + ((size_t)b * (CI - csplit) + (cg - csplit)) * PP;
#pragma unroll
        for (int k = 0; k < 9; k++) {
            const int iy = warp + 8*k;
            const int gy = iy - 1;
            const bool rowok = (iy < 65) & ((unsigned)gy < HH);
            const float* rowp = src + gy * WW;
            pfA[k] = (rowok && (unsigned)(lane - 1) < WW) ? rowp[lane - 1] : 0.f;
            pfB[k] = (rowok && lane + 31 < WW)            ? rowp[lane + 31] : 0.f;
            pfE[k] = (rowok && lane == 0)                 ? rowp[63]        : 0.f;
        }
        if (wme) wv = wgt[((size_t)(ocg*16 + woc) * CI + cg) * 9 + wkk];
    };
    auto store_chunk = [&](int bf) {
#pragma unroll
        for (int k = 0; k < 9; k++) {
            const int iy = warp + 8*k;
            if (k < 8 || iy < 65) {
                float* srow = &s_in[bf][iy][0];
                srow[lane]      = pfA[k];
                srow[lane + 32] = pfB[k];
                if (lane == 0) srow[64] = pfE[k];
            }
        }
        if (wme) ((float*)&s_w[bf][woc >> 1][wk*4 + wt])[woc & 1] = wv;
    };

    load_chunk(0);
    store_chunk(0);
    __syncthreads();

    for (int c = 0; c < CI; c++) {
        const int bf = c & 1;
        if (c + 1 < CI) load_chunk(c + 1);

#pragma unroll
        for (int k = 0; k < 3; k++) {
            const float4* rp = (const float4*)&s_in[bf][2*ty + k][8*tx];
            const float4 ra = rp[0], rb = rp[1], rc = rp[2];
            u64 rs[9];
            rs[0] = splat(ra.x); rs[1] = splat(ra.y); rs[2] = splat(ra.z); rs[3] = splat(ra.w);
            rs[4] = splat(rb.x); rs[5] = splat(rb.y); rs[6] = splat(rb.z); rs[7] = splat(rb.w);
            rs[8] = splat(rc.x);
#pragma unroll
            for (int o2 = 0; o2 < 8; o2++) {
                const ulonglong2 w01 = *(const ulonglong2*)&s_w[bf][o2][k*4];
                const u64 w2 = s_w[bf][o2][k*4 + 2];
#pragma unroll
                for (int j = 0; j < 4; j++) {
                    fma2(acc2[o2][j], rs[2*j],     w01.x);
                    fma2(acc2[o2][j], rs[2*j + 1], w01.y);
                    fma2(acc2[o2][j], rs[2*j + 2], w2);
                }
            }
        }

        if (c + 1 < CI) store_chunk(bf ^ 1);
        __syncthreads();
    }

#pragma unroll
    for (int o2 = 0; o2 < 8; o2++) {
        const float b0 = bias[ocg*16 + 2*o2];
        const float b1 = bias[ocg*16 + 2*o2 + 1];
        float r0[4], r1[4];
#pragma unroll
        for (int j = 0; j < 4; j++) {
            float2 v = unpk(acc2[o2][j]);
            r0[j] = lrelu(v.x + b0);
            r1[j] = lrelu(v.y + b1);
        }
        size_t oo0 = (((size_t)b * OCH + ocg*16 + 2*o2)     * OH + ty) * OW + tx*4;
        size_t oo1 = (((size_t)b * OCH + ocg*16 + 2*o2 + 1) * OH + ty) * OW + tx*4;
        *(float4*)(out + oo0) = make_float4(r0[0], r0[1], r0[2], r0[3]);
        *(float4*)(out + oo1) = make_float4(r1[0], r1[1], r1[2], r1[3]);
    }
}

// ---------------------------------------------------------------------------
// RoIAlign(full image, 32x32 bins, sampling_ratio=2) of prev*attn -> slice 2.
// ---------------------------------------------------------------------------
__global__ void bo3_kernel(const float* __restrict__ prev,
                           const float* __restrict__ attn,
                           float* __restrict__ out /* slice-2 base */)
{
    const int idx = blockIdx.x * 256 + threadIdx.x;
    const int ox = idx & 31, oy = (idx >> 5) & 31, bc = idx >> 10;
    const int b = bc >> 7;
    const float* pv = prev + (size_t)bc * PP;
    const float* at = attn + (size_t)b * PP;
    const float BIN = 63.0f / 32.0f;

    float acc = 0.f;
#pragma unroll
    for (int sy = 0; sy < 2; sy++) {
        const float ys = ((float)oy + 0.25f + 0.5f * sy) * BIN;
        const int y0 = (int)ys;
        const int y1 = min(y0 + 1, HH - 1);
        const float ly = ys - (float)y0, hy = 1.f - ly;
#pragma unroll
        for (int sx = 0; sx < 2; sx++) {
            const float xs = ((float)ox + 0.25f + 0.5f * sx) * BIN;
            const int x0 = (int)xs;
            const int x1 = min(x0 + 1, WW - 1);
            const float lx = xs - (float)x0, hx = 1.f - lx;
            const float f00 = pv[y0*WW + x0] * at[y0*WW + x0];
            const float f01 = pv[y0*WW + x1] * at[y0*WW + x1];
            const float f10 = pv[y1*WW + x0] * at[y1*WW + x0];
            const float f11 = pv[y1*WW + x1] * at[y1*WW + x1];
            acc += hy * (hx * f00 + lx * f01) + ly * (hx * f10 + lx * f11);
        }
    }
    out[idx] = acc * 0.25f;
}

// ---------------------------------------------------------------------------
// slice0 = RoIAlign(l2) + aux + slice1 + slice2
// ---------------------------------------------------------------------------
__global__ void combine_kernel(const float* __restrict__ l2,
                               const float* __restrict__ aux,
                               float* __restrict__ out /* full d_out */)
{
    const int idx = blockIdx.x * 256 + threadIdx.x;
    const int ox = idx & 31, oy = (idx >> 5) & 31, bc = idx >> 10;
    const float* src = l2 + (size_t)bc * PP;
    const float BIN = 63.0f / 32.0f;

    float acc = 0.f;
#pragma unroll
    for (int sy = 0; sy < 2; sy++) {
        const float ys = ((float)oy + 0.25f + 0.5f * sy) * BIN;
        const int y0 = (int)ys;
        const int y1 = min(y0 + 1, HH - 1);
        const float ly = ys - (float)y0, hy = 1.f - ly;
#pragma unroll
        for (int sx = 0; sx < 2; sx++) {
            const float xs = ((float)ox + 0.25f + 0.5f * sx) * BIN;
            const int x0 = (int)xs;
            const int x1 = min(x0 + 1, WW - 1);
            const float lx = xs - (float)x0, hx = 1.f - lx;
            acc += hy * (hx * src[y0*WW + x0] + lx * src[y0*WW + x1])
                 + ly * (hx * src[y1*WW + x0] + lx * src[y1*WW + x1]);
        }
    }
    out[idx] = acc * 0.25f + aux[idx] + out[SLICE + idx] + out[2*SLICE + idx];
}

// ---------------------------------------------------------------------------
// Launch DAG with stream fork/join (capture-legal):
//   main:  conv1 -> conv2 -> conv3 -> conv_aux --------(join B,C)-> combine
//   B:     attn -> conv_prev -> bo3
//   C (forked after conv2): conv_b2
// ---------------------------------------------------------------------------
extern "C" void kernel_launch(void* const* d_in, const int* in_sizes, int n_in,
                              void* d_out, int out_size)
{
    const float* out1   = (const float*)d_in[0];
    const float* out2   = (const float*)d_in[1];
    const float* out3   = (const float*)d_in[2];
    const float* w1     = (const float*)d_in[3];
    const float* b1     = (const float*)d_in[4];
    const float* w2     = (const float*)d_in[5];
    const float* b2     = (const float*)d_in[6];
    const float* w3     = (const float*)d_in[7];
    const float* b3     = (const float*)d_in[8];
    const float* w_aux  = (const float*)d_in[9];
    const float* b_aux  = (const float*)d_in[10];
    const float* w_b2   = (const float*)d_in[11];
    const float* b_b2   = (const float*)d_in[12];
    const float* w_prev = (const float*)d_in[13];
    const float* b_prev = (const float*)d_in[14];
    const float* lin_w  = (const float*)d_in[15];
    const float* lin_b  = (const float*)d_in[16];
    float* out = (float*)d_out;

    float *l1, *l2, *l3, *prev, *aux, *attn;
    cudaGetSymbolAddress((void**)&l1,   g_l1);
    cudaGetSymbolAddress((void**)&l2,   g_l2);
    cudaGetSymbolAddress((void**)&l3,   g_l3);
    cudaGetSymbolAddress((void**)&prev, g_prev);
    cudaGetSymbolAddress((void**)&aux,  g_aux);
    cudaGetSymbolAddress((void**)&attn, g_attn);

    // side streams + events (created once; no device memory involved)
    static cudaStream_t sB = nullptr, sC = nullptr;
    static cudaEvent_t  eFork = nullptr, eL2 = nullptr, eB = nullptr, eC = nullptr;
    if (!sB) {
        cudaStreamCreateWithFlags(&sB, cudaStreamNonBlocking);
        cudaStreamCreateWithFlags(&sC, cudaStreamNonBlocking);
        cudaEventCreateWithFlags(&eFork, cudaEventDisableTiming);
        cudaEventCreateWithFlags(&eL2,   cudaEventDisableTiming);
        cudaEventCreateWithFlags(&eB,    cudaEventDisableTiming);
        cudaEventCreateWithFlags(&eC,    cudaEventDisableTiming);
    }

    const dim3 gs1(2, OCH/8, BB);    // stride-1 convs
    const dim3 gs2(1, OCH/16, BB);   // stride-2 convs: 16 oc per block
    const int  nPix = (int)(SLICE / 256);

    // fork B from main at entry
    cudaEventRecord(eFork, 0);
    cudaStreamWaitEvent(sB, eFork, 0);

    // ---- stream B: attn -> conv_prev -> bo3 (independent of l1/l2/l3) ----
    attn_kernel<<<BB, 256, 0, sB>>>(out1, lin_w, lin_b, attn);
    conv_s1<128><<<gs1, 256, 0, sB>>>(out2, out3, 64, w_prev, b_prev, prev);
    bo3_kernel<<<nPix, 256, 0, sB>>>(prev, attn, out + 2*SLICE);   // slice 2
    cudaEventRecord(eB, sB);

    // ---- main chain ----
    conv_s1<64 ><<<gs1, 256>>>(out1, nullptr, 64,  w1, b1, l1);
    conv_s1<128><<<gs1, 256>>>(l1,   nullptr, 128, w2, b2, l2);

    // fork C after conv2: conv_b2 needs only l1,l2
    cudaEventRecord(eL2, 0);
    cudaStreamWaitEvent(sC, eL2, 0);
    conv_s2<256><<<gs2, 256, 0, sC>>>(l1, l2, 128, w_b2, b_b2, out + SLICE);  // slice 1
    cudaEventRecord(eC, sC);

    conv_s1<128><<<gs1, 256>>>(l2, nullptr, 128, w3,    b3,    l3);
    conv_s2<128><<<gs2, 256>>>(l3, nullptr, 128, w_aux, b_aux, aux);

    // join B and C into main, then combine
    cudaStreamWaitEvent(0, eB, 0);
    cudaStreamWaitEvent(0, eC, 0);
    combine_kernel<<<nPix, 256>>>(l2, aux, out);                    // slice 0
}

// round 10
// speedup vs baseline: 1.7091x; 1.0018x over previous
#include <cuda_runtime.h>

// Problem constants
#define BB   32
#define CIN  64
#define OCH  128
#define HH   64
#define WW   64
#define PP   (HH*WW)          // 4096 pixels
#define OH   32
#define OW   32
#define SLICE ((size_t)BB*OCH*OH*OW)   // elements per output slice

typedef unsigned long long u64;

// Scratch (device globals: no allocation allowed in kernel_launch)
__device__ float g_l1  [BB*OCH*HH*WW];
__device__ float g_l2  [BB*OCH*HH*WW];
__device__ float g_l3  [BB*OCH*HH*WW];
__device__ float g_prev[BB*OCH*HH*WW];
__device__ float g_aux [BB*OCH*OH*OW];
__device__ float g_attn[BB*PP];

__device__ __forceinline__ float lrelu(float x) { return x >= 0.f ? x : 0.1f * x; }

// ---- packed f32x2 helpers (sm_103a) -----------------------------------
__device__ __forceinline__ u64 pk2(float lo, float hi) {
    u64 r; asm("mov.b64 %0,{%1,%2};" : "=l"(r) : "f"(lo), "f"(hi)); return r;
}
__device__ __forceinline__ u64 splat(float v) { return pk2(v, v); }
__device__ __forceinline__ void fma2(u64& d, u64 a, u64 b) {
    asm("fma.rn.f32x2 %0,%1,%2,%0;" : "+l"(d) : "l"(a), "l"(b));
}
__device__ __forceinline__ float2 unpk(u64 v) {
    float2 r; asm("mov.b64 {%0,%1},%2;" : "=f"(r.x), "=f"(r.y) : "l"(v)); return r;
}

// ---------------------------------------------------------------------------
// Attention: logits[b,p] = <lin_w[p,:], out1[b,:,p]> + lin_b[p]; softmax over p.
// ---------------------------------------------------------------------------
__global__ void attn_kernel(const float* __restrict__ out1,
                            const float* __restrict__ lin_w,
                            const float* __restrict__ lin_b,
                            float* __restrict__ attn)
{
    const int b   = blockIdx.x;
    const int tid = threadIdx.x;
    const float* xb = out1 + (size_t)b * CIN * PP;

    float logit[16];
    float lmax = -1e30f;
#pragma unroll
    for (int i = 0; i < 16; i++) {
        const int p = tid + i * 256;
        float acc = lin_b[p];
        const float4* wr = (const float4*)(lin_w + (size_t)p * CIN);
#pragma unroll
        for (int c4 = 0; c4 < CIN / 4; c4++) {
            float4 w4 = wr[c4];
            acc = fmaf(w4.x, xb[(c4*4+0)*PP + p], acc);
            acc = fmaf(w4.y, xb[(c4*4+1)*PP + p], acc);
            acc = fmaf(w4.z, xb[(c4*4+2)*PP + p], acc);
            acc = fmaf(w4.w, xb[(c4*4+3)*PP + p], acc);
        }
        logit[i] = acc;
        lmax = fmaxf(lmax, acc);
    }

    __shared__ float red[256];
    red[tid] = lmax; __syncthreads();
    for (int s = 128; s > 0; s >>= 1) {
        if (tid < s) red[tid] = fmaxf(red[tid], red[tid + s]);
        __syncthreads();
    }
    const float m = red[0]; __syncthreads();

    float lsum = 0.f;
#pragma unroll
    for (int i = 0; i < 16; i++) { logit[i] = expf(logit[i] - m); lsum += logit[i]; }
    red[tid] = lsum; __syncthreads();
    for (int s = 128; s > 0; s >>= 1) {
        if (tid < s) red[tid] += red[tid + s];
        __syncthreads();
    }
    const float inv = 1.0f / red[0];
#pragma unroll
    for (int i = 0; i < 16; i++)
        attn[(size_t)b * PP + tid + i * 256] = logit[i] * inv;
}

// ---------------------------------------------------------------------------
// Stride-1 3x3 conv + bias + lrelu, f32x2 over oc pairs, software-pipelined:
// per ci-step: prefetch next ci to registers, compute current from smem buf,
// store prefetch to other buf, ONE barrier. Fill latency fully hidden.
// Block: tile 32 rows x 64 cols, 8 oc (4 pairs), 256 threads.
// ---------------------------------------------------------------------------
template<int CI>
__global__ __launch_bounds__(256, 2)
void conv_s1(const float* __restrict__ in0, const float* __restrict__ in1, int csplit,
             const float* __restrict__ wgt, const float* __restrict__ bias,
             float* __restrict__ out)
{
    __shared__ __align__(16) float s_in[2][34][68];   // double-buffered 1-ci tile
    __shared__ __align__(16) u64   s_w[2][4][12];     // [buf][oc2][k*4+t]

    const int tid  = threadIdx.x;
    const int tx   = tid & 7;
    const int ty   = tid >> 3;
    const int x8   = tx * 8;
    const int ty0  = blockIdx.x * 32;
    const int ocg  = blockIdx.y;
    const int b    = blockIdx.z;
    const int warp = tid >> 5;
    const int lane = tid & 31;

    // weight element handled by this thread (fixed across chunks)
    const int woc = tid / 9, wkk = tid - woc * 9;
    const int wk  = wkk / 3, wt = wkk - wk * 3;
    const bool wme = tid < 72;

    u64 acc2[4][8];
#pragma unroll
    for (int o = 0; o < 4; o++)
#pragma unroll
        for (int j = 0; j < 8; j++) acc2[o][j] = 0ULL;

    float pfA[5], pfB[5], pfE[5], wv = 0.f;

    auto load_chunk = [&](int cg) {
        const float* src = (cg < csplit)
            ? in0 + ((size_t)b * csplit + cg) * PP
            : in1 + ((size_t)b * (CI - csplit) + (cg - csplit)) * PP;
#pragma unroll
        for (int k = 0; k < 5; k++) {
            const int iy = warp + 8*k;
            const int gy = ty0 - 1 + iy;
            const bool rowok = (iy < 34) & ((unsigned)gy < HH);
            const float* rowp = src + gy * WW;
            pfA[k] = (rowok && (unsigned)(lane - 1) < WW) ? rowp[lane - 1] : 0.f;
            pfB[k] = (rowok && lane + 31 < WW)            ? rowp[lane + 31] : 0.f;
            pfE[k] = (rowok && lane < 2 && lane + 63 < WW)? rowp[lane + 63] : 0.f;
        }
        if (wme) wv = wgt[((size_t)(ocg*8 + woc) * CI + cg) * 9 + wkk];
    };
    auto store_chunk = [&](int bf) {
#pragma unroll
        for (int k = 0; k < 5; k++) {
            const int iy = warp + 8*k;
            if (k < 4 || iy < 34) {
                float* srow = &s_in[bf][iy][0];
                srow[lane]      = pfA[k];
                srow[lane + 32] = pfB[k];
                if (lane < 2) srow[lane + 64] = pfE[k];
            }
        }
        if (wme) ((float*)&s_w[bf][woc >> 1][wk*4 + wt])[woc & 1] = wv;
    };

    // prologue
    load_chunk(0);
    store_chunk(0);
    __syncthreads();

    for (int c = 0; c < CI; c++) {
        const int bf = c & 1;
        if (c + 1 < CI) load_chunk(c + 1);          // LDG only, no consumer yet

        // compute chunk c
#pragma unroll
        for (int k = 0; k < 3; k++) {
            const float4* rp = (const float4*)&s_in[bf][ty + k][x8];
            const float4 ra = rp[0], rb = rp[1], rc = rp[2];
            u64 rs[10];
            rs[0] = splat(ra.x); rs[1] = splat(ra.y); rs[2] = splat(ra.z); rs[3] = splat(ra.w);
            rs[4] = splat(rb.x); rs[5] = splat(rb.y); rs[6] = splat(rb.z); rs[7] = splat(rb.w);
            rs[8] = splat(rc.x); rs[9] = splat(rc.y);
#pragma unroll
            for (int o2 = 0; o2 < 4; o2++) {
                const ulonglong2 w01 = *(const ulonglong2*)&s_w[bf][o2][k*4];
                const u64 w2 = s_w[bf][o2][k*4 + 2];
#pragma unroll
                for (int j = 0; j < 8; j++) {
                    fma2(acc2[o2][j], rs[j],     w01.x);
                    fma2(acc2[o2][j], rs[j + 1], w01.y);
                    fma2(acc2[o2][j], rs[j + 2], w2);
                }
            }
        }

        if (c + 1 < CI) store_chunk(bf ^ 1);        // other buffer: no WAR
        __syncthreads();
    }

#pragma unroll
    for (int o2 = 0; o2 < 4; o2++) {
        const float b0 = bias[ocg*8 + 2*o2];
        const float b1 = bias[ocg*8 + 2*o2 + 1];
        float r0[8], r1[8];
#pragma unroll
        for (int j = 0; j < 8; j++) {
            float2 v = unpk(acc2[o2][j]);
            r0[j] = lrelu(v.x + b0);
            r1[j] = lrelu(v.y + b1);
        }
        size_t o0 = (((size_t)b * OCH + ocg*8 + 2*o2)     * HH + ty0 + ty) * WW + x8;
        size_t o1 = (((size_t)b * OCH + ocg*8 + 2*o2 + 1) * HH + ty0 + ty) * WW + x8;
        *(float4*)(out + o0)     = make_float4(r0[0], r0[1], r0[2], r0[3]);
        *(float4*)(out + o0 + 4) = make_float4(r0[4], r0[5], r0[6], r0[7]);
        *(float4*)(out + o1)     = make_float4(r1[0], r1[1], r1[2], r1[3]);
        *(float4*)(out + o1 + 4) = make_float4(r1[4], r1[5], r1[6], r1[7]);
    }
}

// ---------------------------------------------------------------------------
// Stride-2 3x3 conv + bias + lrelu (pad 1), out 32x32, pipelined like conv_s1.
// Block: 16 oc (8 pairs), 256 threads; thread: 1 out row x 4 cols x 8 pairs.
// ---------------------------------------------------------------------------
template<int CI>
__global__ __launch_bounds__(256, 2)
void conv_s2(const float* __restrict__ in0, const float* __restrict__ in1, int csplit,
             const float* __restrict__ wgt, const float* __restrict__ bias,
             float* __restrict__ out)
{
    __shared__ __align__(16) float s_in[2][65][68];   // rows -1..63, cols -1..63
    __shared__ __align__(16) u64   s_w[2][8][12];     // [buf][oc2][k*4+t]

    const int tid  = threadIdx.x;
    const int tx   = tid & 7;           // out col group (4 cols)
    const int ty   = tid >> 3;          // 0..31 out row
    const int ocg  = blockIdx.y;        // 0..7
    const int b    = blockIdx.z;
    const int warp = tid >> 5;
    const int lane = tid & 31;

    const int woc = tid / 9, wkk = tid - woc * 9;
    const int wk  = wkk / 3, wt = wkk - wk * 3;
    const bool wme = tid < 144;         // 16 oc x 9

    u64 acc2[8][4];
#pragma unroll
    for (int o = 0; o < 8; o++)
#pragma unroll
        for (int j = 0; j < 4; j++) acc2[o][j] = 0ULL;

    float pfA[9], pfB[9], pfE[9], wv = 0.f;

    auto load_chunk = [&](int cg) {
        const float* src = (cg < csplit)
            ? in0 + ((size_t)b * csplit + cg) * PP
            : in1 + ((size_t)b * (CI - csplit) + (cg - csplit)) * PP;
#pragma unroll
        for (int k = 0; k < 9; k++) {
            const int iy = warp + 8*k;
            const int gy = iy - 1;
            const bool rowok = (iy < 65) & ((unsigned)gy < HH);
            const float* rowp = src + gy * WW;
            pfA[k] = (rowok && (unsigned)(lane - 1) < WW) ? rowp[lane - 1] : 0.f;
            pfB[k] = (rowok && lane + 31 < WW)            ? rowp[lane + 31] : 0.f;
            pfE[k] = (rowok && lane == 0)                 ? rowp[63]        : 0.f;
        }
        if (wme) wv = wgt[((size_t)(ocg*16 + woc) * CI + cg) * 9 + wkk];
    };
    auto store_chunk = [&](int bf) {
#pragma unroll
        for (int k = 0; k < 9; k++) {
            const int iy = warp + 8*k;
            if (k < 8 || iy < 65) {
                float* srow = &s_in[bf][iy][0];
                srow[lane]      = pfA[k];
                srow[lane + 32] = pfB[k];
                if (lane == 0) srow[64] = pfE[k];
            }
        }
        if (wme) ((float*)&s_w[bf][woc >> 1][wk*4 + wt])[woc & 1] = wv;
    };

    load_chunk(0);
    store_chunk(0);
    __syncthreads();

    for (int c = 0; c < CI; c++) {
        const int bf = c & 1;
        if (c + 1 < CI) load_chunk(c + 1);

#pragma unroll
        for (int k = 0; k < 3; k++) {
            const float4* rp = (const float4*)&s_in[bf][2*ty + k][8*tx];
            const float4 ra = rp[0], rb = rp[1], rc = rp[2];
            u64 rs[9];
            rs[0] = splat(ra.x); rs[1] = splat(ra.y); rs[2] = splat(ra.z); rs[3] = splat(ra.w);
            rs[4] = splat(rb.x); rs[5] = splat(rb.y); rs[6] = splat(rb.z); rs[7] = splat(rb.w);
            rs[8] = splat(rc.x);
#pragma unroll
            for (int o2 = 0; o2 < 8; o2++) {
                const ulonglong2 w01 = *(const ulonglong2*)&s_w[bf][o2][k*4];
                const u64 w2 = s_w[bf][o2][k*4 + 2];
#pragma unroll
                for (int j = 0; j < 4; j++) {
                    fma2(acc2[o2][j], rs[2*j],     w01.x);
                    fma2(acc2[o2][j], rs[2*j + 1], w01.y);
                    fma2(acc2[o2][j], rs[2*j + 2], w2);
                }
            }
        }

        if (c + 1 < CI) store_chunk(bf ^ 1);
        __syncthreads();
    }

#pragma unroll
    for (int o2 = 0; o2 < 8; o2++) {
        const float b0 = bias[ocg*16 + 2*o2];
        const float b1 = bias[ocg*16 + 2*o2 + 1];
        float r0[4], r1[4];
#pragma unroll
        for (int j = 0; j < 4; j++) {
            float2 v = unpk(acc2[o2][j]);
            r0[j] = lrelu(v.x + b0);
            r1[j] = lrelu(v.y + b1);
        }
        size_t oo0 = (((size_t)b * OCH + ocg*16 + 2*o2)     * OH + ty) * OW + tx*4;
        size_t oo1 = (((size_t)b * OCH + ocg*16 + 2*o2 + 1) * OH + ty) * OW + tx*4;
        *(float4*)(out + oo0) = make_float4(r0[0], r0[1], r0[2], r0[3]);
        *(float4*)(out + oo1) = make_float4(r1[0], r1[1], r1[2], r1[3]);
    }
}

// ---------------------------------------------------------------------------
// RoIAlign(full image, 32x32 bins, sampling_ratio=2) of prev*attn -> slice 2.
// ---------------------------------------------------------------------------
__global__ void bo3_kernel(const float* __restrict__ prev,
                           const float* __restrict__ attn,
                           float* __restrict__ out /* slice-2 base */)
{
    const int idx = blockIdx.x * 256 + threadIdx.x;
    const int ox = idx & 31, oy = (idx >> 5) & 31, bc = idx >> 10;
    const int b = bc >> 7;
    const float* pv = prev + (size_t)bc * PP;
    const float* at = attn + (size_t)b * PP;
    const float BIN = 63.0f / 32.0f;

    float acc = 0.f;
#pragma unroll
    for (int sy = 0; sy < 2; sy++) {
        const float ys = ((float)oy + 0.25f + 0.5f * sy) * BIN;
        const int y0 = (int)ys;
        const int y1 = min(y0 + 1, HH - 1);
        const float ly = ys - (float)y0, hy = 1.f - ly;
#pragma unroll
        for (int sx = 0; sx < 2; sx++) {
            const float xs = ((float)ox + 0.25f + 0.5f * sx) * BIN;
            const int x0 = (int)xs;
            const int x1 = min(x0 + 1, WW - 1);
            const float lx = xs - (float)x0, hx = 1.f - lx;
            const float f00 = pv[y0*WW + x0] * at[y0*WW + x0];
            const float f01 = pv[y0*WW + x1] * at[y0*WW + x1];
            const float f10 = pv[y1*WW + x0] * at[y1*WW + x0];
            const float f11 = pv[y1*WW + x1] * at[y1*WW + x1];
            acc += hy * (hx * f00 + lx * f01) + ly * (hx * f10 + lx * f11);
        }
    }
    out[idx] = acc * 0.25f;
}

// ---------------------------------------------------------------------------
// slice0 = RoIAlign(l2) + aux + slice1 + slice2
// ---------------------------------------------------------------------------
__global__ void combine_kernel(const float* __restrict__ l2,
                               const float* __restrict__ aux,
                               float* __restrict__ out /* full d_out */)
{
    const int idx = blockIdx.x * 256 + threadIdx.x;
    const int ox = idx & 31, oy = (idx >> 5) & 31, bc = idx >> 10;
    const float* src = l2 + (size_t)bc * PP;
    const float BIN = 63.0f / 32.0f;

    float acc = 0.f;
#pragma unroll
    for (int sy = 0; sy < 2; sy++) {
        const float ys = ((float)oy + 0.25f + 0.5f * sy) * BIN;
        const int y0 = (int)ys;
        const int y1 = min(y0 + 1, HH - 1);
        const float ly = ys - (float)y0, hy = 1.f - ly;
#pragma unroll
        for (int sx = 0; sx < 2; sx++) {
            const float xs = ((float)ox + 0.25f + 0.5f * sx) * BIN;
            const int x0 = (int)xs;
            const int x1 = min(x0 + 1, WW - 1);
            const float lx = xs - (float)x0, hx = 1.f - lx;
            acc += hy * (hx * src[y0*WW + x0] + lx * src[y0*WW + x1])
                 + ly * (hx * src[y1*WW + x0] + lx * src[y1*WW + x1]);
        }
    }
    out[idx] = acc * 0.25f + aux[idx] + out[SLICE + idx] + out[2*SLICE + idx];
}

// ---------------------------------------------------------------------------
// Launch DAG with stream fork/join (capture-legal):
//   main:  conv1 -> conv2 -> conv3 -> conv_aux --------(join B,C)-> combine
//   B:     attn -> conv_prev -> bo3
//   C (forked after conv2): conv_b2
// ---------------------------------------------------------------------------
extern "C" void kernel_launch(void* const* d_in, const int* in_sizes, int n_in,
                              void* d_out, int out_size)
{
    const float* out1   = (const float*)d_in[0];
    const float* out2   = (const float*)d_in[1];
    const float* out3   = (const float*)d_in[2];
    const float* w1     = (const float*)d_in[3];
    const float* b1     = (const float*)d_in[4];
    const float* w2     = (const float*)d_in[5];
    const float* b2     = (const float*)d_in[6];
    const float* w3     = (const float*)d_in[7];
    const float* b3     = (const float*)d_in[8];
    const float* w_aux  = (const float*)d_in[9];
    const float* b_aux  = (const float*)d_in[10];
    const float* w_b2   = (const float*)d_in[11];
    const float* b_b2   = (const float*)d_in[12];
    const float* w_prev = (const float*)d_in[13];
    const float* b_prev = (const float*)d_in[14];
    const float* lin_w  = (const float*)d_in[15];
    const float* lin_b  = (const float*)d_in[16];
    float* out = (float*)d_out;

    float *l1, *l2, *l3, *prev, *aux, *attn;
    cudaGetSymbolAddress((void**)&l1,   g_l1);
    cudaGetSymbolAddress((void**)&l2,   g_l2);
    cudaGetSymbolAddress((void**)&l3,   g_l3);
    cudaGetSymbolAddress((void**)&prev, g_prev);
    cudaGetSymbolAddress((void**)&aux,  g_aux);
    cudaGetSymbolAddress((void**)&attn, g_attn);

    // side streams + events (created once; no device memory involved)
    static cudaStream_t sB = nullptr, sC = nullptr;
    static cudaEvent_t  eFork = nullptr, eL2 = nullptr, eB = nullptr, eC = nullptr;
    if (!sB) {
        cudaStreamCreateWithFlags(&sB, cudaStreamNonBlocking);
        cudaStreamCreateWithFlags(&sC, cudaStreamNonBlocking);
        cudaEventCreateWithFlags(&eFork, cudaEventDisableTiming);
        cudaEventCreateWithFlags(&eL2,   cudaEventDisableTiming);
        cudaEventCreateWithFlags(&eB,    cudaEventDisableTiming);
        cudaEventCreateWithFlags(&eC,    cudaEventDisableTiming);
    }

    const dim3 gs1(2, OCH/8, BB);    // stride-1 convs
    const dim3 gs2(1, OCH/16, BB);   // stride-2 convs: 16 oc per block
    const int  nPix = (int)(SLICE / 256);

    // fork B from main at entry
    cudaEventRecord(eFork, 0);
    cudaStreamWaitEvent(sB, eFork, 0);

    // ---- stream B: attn -> conv_prev -> bo3 (independent of l1/l2/l3) ----
    attn_kernel<<<BB, 256, 0, sB>>>(out1, lin_w, lin_b, attn);
    conv_s1<128><<<gs1, 256, 0, sB>>>(out2, out3, 64, w_prev, b_prev, prev);
    bo3_kernel<<<nPix, 256, 0, sB>>>(prev, attn, out + 2*SLICE);   // slice 2
    cudaEventRecord(eB, sB);

    // ---- main chain ----
    conv_s1<64 ><<<gs1, 256>>>(out1, nullptr, 64,  w1, b1, l1);
    conv_s1<128><<<gs1, 256>>>(l1,   nullptr, 128, w2, b2, l2);

    // fork C after conv2: conv_b2 needs only l1,l2
    cudaEventRecord(eL2, 0);
    cudaStreamWaitEvent(sC, eL2, 0);
    conv_s2<256><<<gs2, 256, 0, sC>>>(l1, l2, 128, w_b2, b_b2, out + SLICE);  // slice 1
    cudaEventRecord(eC, sC);

    conv_s1<128><<<gs1, 256>>>(l2, nullptr, 128, w3,    b3,    l3);
    conv_s2<128><<<gs2, 256>>>(l3, nullptr, 128, w_aux, b_aux, aux);

    // join B and C into main, then combine
    cudaStreamWaitEvent(0, eB, 0);
    cudaStreamWaitEvent(0, eC, 0);
    combine_kernel<<<nPix, 256>>>(l2, aux, out);                    // slice 0
}